// round 15
// baseline (speedup 1.0000x reference)
#include <cuda_runtime.h>
#include <math.h>
#include <stdint.h>

#define T_   128
#define B_   64
#define E_   128
#define D_   128
#define H_   256
#define V_   8000
#define NCTA 128
#define NTHR 256

// ---------------- persistent device state ----------------
__device__ float g_hx[2][B_*H_];     // double-buffered hidden state
__device__ float g_rx[B_*D_];        // stack read vector
__device__ float g_hs[B_*T_*H_];     // all hidden states, [b][t][h]
__device__ unsigned int g_barA;      // grid barrier A counter (hx ready)
__device__ unsigned int g_barB;      // grid barrier B counter (rx ready)

__device__ __forceinline__ float sigm(float x)   { return 1.0f / (1.0f + __expf(-x)); }
__device__ __forceinline__ float tanh_f(float x) { return 2.0f / (1.0f + __expf(-2.0f*x)) - 1.0f; }
__device__ __forceinline__ float tf32r(float x) {
    float y; asm("cvt.rna.tf32.f32 %0, %1;" : "=f"(y) : "f"(x)); return y;
}

// fp32-accum tf32 tensor-core MMA (sm_80+ portable; compiles for compute_103)
__device__ __forceinline__ void mma_tf32_16x8x8(float* d, const uint32_t* a,
                                                const uint32_t* b) {
    asm volatile(
        "mma.sync.aligned.m16n8k8.row.col.f32.tf32.tf32.f32 "
        "{%0,%1,%2,%3}, {%4,%5,%6,%7}, {%8,%9}, {%0,%1,%2,%3};\n"
        : "+f"(d[0]), "+f"(d[1]), "+f"(d[2]), "+f"(d[3])
        : "r"(a[0]), "r"(a[1]), "r"(a[2]), "r"(a[3]),
          "r"(b[0]), "r"(b[1]));
}

// ---------------- setup ----------------
__global__ void setup_kernel() {
    int tid = blockIdx.x * blockDim.x + threadIdx.x;
    int stride = gridDim.x * blockDim.x;
    if (tid == 0) { g_barA = 0u; g_barB = 0u; }
    for (int i = tid; i < B_*H_; i += stride) g_hx[0][i] = 0.f;
    for (int i = tid; i < B_*D_; i += stride) g_rx[i] = 1.f;
}

// ---------------- persistent recurrence kernel ----------------
// 128 CTAs x 256 thr, 1 CTA/SM. CTA j owns h-units 2j,2j+1 (8 gate rows).
// Gate GEMM on tensor cores: D[64b x 8n] tf32 mma, A = staged inputs (chunkT,
// [k][b]), B = weights WgT[k][n]. Warps: mt = wrp&3 (m16 batch tile),
// kh = wrp>>2 (K-half); halves reduced via SMEM.
// Chunk order emb, hx_lo, hx_hi, rx; barrier-B wait deferred to chunk 2;
// barrier-A wait deferred behind emb(t+1) prefetch + suffix-scan-1.
// Stack: CTA c handles batch (c&63), D-half (c>>6). W_valT half in SMEM.
#define WTP  9     // WgT pitch [k][n]
#define CHP  68    // chunkT pitch [k][b]
#define REDP 544   // red per-kg pitch (layout kept from R11)
__global__ __launch_bounds__(NTHR, 1)
void recur_kernel(const int*   __restrict__ x,     const float* __restrict__ emb,
                  const float* __restrict__ W_ih,  const float* __restrict__ b_ih,
                  const float* __restrict__ W_hh,  const float* __restrict__ b_hh,
                  const float* __restrict__ W_pop, const float* __restrict__ b_pop,
                  const float* __restrict__ W_push,const float* __restrict__ b_push,
                  const float* __restrict__ b_val, const float* __restrict__ W_val)
{
    extern __shared__ float sm[];
    float* WgT     = sm;                    // 512 x 9 = 4608
    float* biasSh  = WgT + 512*WTP;         // 8
    float* chunkT  = biasSh + 8;            // 128 x 68 = 8704  [k][b]
    float* red     = chunkT + 128*CHP;      // 8 x 544 = 4352
    float* gatesSh = red + 8*REDP;          // 512
    float* cxSh    = gatesSh + 512;         // 128
    float* WvT     = cxSh + 128;            // 256 x 65 = 16640
    float* Vb      = WvT + 16640;           // 128 x 64 = 8192
    float* hxSh    = Vb + 8192;             // 256
    float* sSh     = hxSh + 256;            // 128
    float* snewSh  = sSh + 128;             // 128
    float* wSh     = snewSh + 128;          // 128
    float* partial = wSh + 128;             // 256
    float* scal    = partial + 256;         // 2
    float* wtot    = scal + 2;              // 8

    const int tid = threadIdx.x;
    const int cta = blockIdx.x;
    const int h0  = cta * 2;
    const int sb  = cta & 63;    // stack batch
    const int dh  = cta >> 6;    // stack D-half

    // gate weights transposed [k][n], tf32-rounded (constant over t)
    for (int idx = tid; idx < 8*512; idx += NTHR) {
        int k = idx >> 3, r = idx & 7;
        int n = (r >> 1) * H_ + h0 + (r & 1);
        float v = (k < 256) ? W_ih[n*256 + k] : W_hh[n*256 + (k - 256)];
        WgT[k*WTP + r] = tf32r(v);
    }
    // W_valT half: WvT[k*65 + dl] = W_val[(dh*64+dl)*H + k]
    for (int idx = tid; idx < 64*256; idx += NTHR) {
        int dl = idx >> 8, k = idx & 255;
        WvT[k*65 + dl] = W_val[(dh*64 + dl)*H_ + k];
    }
    if (tid < 8) {
        int n = (tid >> 1) * H_ + h0 + (tid & 1);
        biasSh[tid] = b_ih[n] + b_hh[n];
    }
    if (tid < 128) { cxSh[tid] = 0.f; sSh[tid] = 0.f; }
    __syncthreads();

    // staging role: batch sbt, k-quarter kq4 (32 k's per chunk)
    const int sbt = tid & 63, kq4 = tid >> 6;
    const int lane = tid & 31, wrp = tid >> 5;
    // mma role: m16 batch tile + K-half
    const int mt = wrp & 3, kh = wrp >> 2;
    const int b0 = mt*16;
    const int rr = lane >> 2, cq = lane & 3;

    // prefetch emb chunk for t=0
    float4 st[8];
    int tok = x[sbt];
    {
        const float4* s = (const float4*)(emb + (size_t)tok*E_ + kq4*32);
        #pragma unroll
        for (int j = 0; j < 8; j++) st[j] = s[j];
    }

    for (int t = 0; t < T_; t++) {
        const int cur = t & 1, nxt = cur ^ 1;

        // ---------- gate phase: gates = [ex, hx_lo, hx_hi, rx] @ W^T (tf32 mma) ----------
        float dacc[4] = {0.f, 0.f, 0.f, 0.f};

        for (int kc = 0; kc < 4; kc++) {
            // weight-column offset for this chunk: emb, hx_lo, hx_hi, rx
            const int woff = (kc == 0) ? 0 : (kc == 1) ? 256 : (kc == 2) ? 384 : 128;

            // store staged regs transposed (tf32-rounded) into chunkT[k][b]
            #pragma unroll
            for (int j = 0; j < 8; j++) {
                int k = kq4*32 + j*4;
                float* c = chunkT + k*CHP + sbt;
                c[0*CHP] = tf32r(st[j].x);
                c[1*CHP] = tf32r(st[j].y);
                c[2*CHP] = tf32r(st[j].z);
                c[3*CHP] = tf32r(st[j].w);
            }
            __syncthreads();
            // deferred barrier-B wait: rx(t-1) must be published before we
            // prefetch it (chunk 3). ~2 chunks of compute already hid the wait.
            if (kc == 2) {
                if (tid == 0) {
                    while (*((volatile unsigned int*)&g_barB) <
                           (unsigned int)t*NCTA) { }
                    __threadfence();   // invalidate L1 so rx loads see L2
                }
                __syncthreads();
            }
            // prefetch next chunk while computing this one
            if (kc < 3) {
                const float4* s = (kc == 0)
                    ? (const float4*)(g_hx[cur] + sbt*H_ + kq4*32)
                    : (kc == 1)
                    ? (const float4*)(g_hx[cur] + sbt*H_ + 128 + kq4*32)
                    : (const float4*)(g_rx + sbt*D_ + kq4*32);
                #pragma unroll
                for (int j = 0; j < 8; j++) st[j] = s[j];
            }
            // mma compute: this warp covers K-half kh of the chunk (8 k8-steps)
            const int kb = kh*64;
            #pragma unroll
            for (int ks = 0; ks < 8; ks++) {
                const int kl = kb + ks*8;
                uint32_t af[4], bf[2];
                af[0] = __float_as_uint(chunkT[(kl+cq  )*CHP + b0 + rr    ]);
                af[1] = __float_as_uint(chunkT[(kl+cq  )*CHP + b0 + rr + 8]);
                af[2] = __float_as_uint(chunkT[(kl+cq+4)*CHP + b0 + rr    ]);
                af[3] = __float_as_uint(chunkT[(kl+cq+4)*CHP + b0 + rr + 8]);
                const int wk = woff + kl;
                bf[0] = __float_as_uint(WgT[(wk+cq  )*WTP + rr]);
                bf[1] = __float_as_uint(WgT[(wk+cq+4)*WTP + rr]);
                mma_tf32_16x8x8(dacc, af, bf);
            }
            if (kc < 3) __syncthreads();   // protect chunkT overwrite
        }
        // K-half reduction: kh=1 warps publish, kh=0 warps combine + bias
        if (kh == 1)
            *(float4*)&red[(mt*32 + lane)*4] =
                make_float4(dacc[0], dacc[1], dacc[2], dacc[3]);
        __syncthreads();
        if (kh == 0) {
            float4 o = *(const float4*)&red[(mt*32 + lane)*4];
            float bi0 = biasSh[2*cq], bi1 = biasSh[2*cq + 1];
            gatesSh[(2*cq+0)*64 + b0 + rr    ] = dacc[0] + o.x + bi0;
            gatesSh[(2*cq+1)*64 + b0 + rr    ] = dacc[1] + o.y + bi1;
            gatesSh[(2*cq+0)*64 + b0 + rr + 8] = dacc[2] + o.z + bi0;
            gatesSh[(2*cq+1)*64 + b0 + rr + 8] = dacc[3] + o.w + bi1;
        }
        __syncthreads();
        if (tid < 128) {
            int hl = tid >> 6, b = tid & 63;
            float ig = gatesSh[(0 + hl)*64 + b];
            float fg = gatesSh[(2 + hl)*64 + b];
            float gg = gatesSh[(4 + hl)*64 + b];
            float og = gatesSh[(6 + hl)*64 + b];
            int h = h0 + hl;
            float c  = sigm(fg)*cxSh[tid] + sigm(ig)*tanh_f(gg);
            float hv = sigm(og)*tanh_f(c);
            cxSh[tid] = c;
            g_hx[nxt][b*H_ + h] = hv;
            g_hs[b*(T_*H_) + t*H_ + h] = hv;
        }

        if (t == T_ - 1) break;   // rx(127)/s(127) dead; g_hs visible at kernel end

        // ---- barrier A arrive (hx complete) ----
        __syncthreads();
        if (tid == 0) { __threadfence(); atomicAdd(&g_barA, 1u); }

        // hidden work while other CTAs arrive:
        // (1) emb(t+1) prefetch (input-only data)
        tok = x[(t+1)*B_ + sbt];
        {
            const float4* s = (const float4*)(emb + (size_t)tok*E_ + kq4*32);
            #pragma unroll
            for (int j = 0; j < 8; j++) st[j] = s[j];
        }
        // (2) suffix scan 1 over s (CTA-local state from step t-1)
        float sv = 0.f, v1 = 0.f;
        if (tid < 128) {
            sv = sSh[tid]; v1 = sv;
            #pragma unroll
            for (int off = 1; off < 32; off <<= 1) {
                float tv = __shfl_down_sync(0xffffffffu, v1, off);
                if (lane + off < 32) v1 += tv;
            }
            if (lane == 0) wtot[wrp] = v1;
        }

        // ---- barrier A wait ----
        if (tid == 0) {
            while (*((volatile unsigned int*)&g_barA) <
                   (unsigned int)(t + 1)*NCTA) { }
            __threadfence();   // invalidate L1 so hx loads see L2
        }
        __syncthreads();

        // ---------- stack phase (all 128 CTAs; 2 per batch) ----------
        hxSh[tid] = g_hx[nxt][sb*H_ + tid];
        __syncthreads();
        {   // vals matvec: 64 outputs x 256 K, 4-way K split
            int dl = tid & 63, q = tid >> 6;
            const float* wcol = WvT + q*64*65 + dl;
            const float* hq   = hxSh + q*64;
            float a = 0.f;
            #pragma unroll 8
            for (int k = 0; k < 64; k++) a += wcol[k*65] * hq[k];
            partial[tid] = a;
        }
        if (wrp == 6 || wrp == 7) {   // pop / push dots
            const float* wrow = (wrp == 6) ? W_pop : W_push;
            float a = 0.f;
            for (int k = lane; k < H_; k += 32) a += wrow[k]*hxSh[k];
            #pragma unroll
            for (int off = 16; off > 0; off >>= 1)
                a += __shfl_xor_sync(0xffffffffu, a, off);
            if (lane == 0) scal[wrp - 6] = a + ((wrp == 6) ? b_pop[0] : b_push[0]);
        }
        __syncthreads();
        float pop  = sigm(scal[0]);
        float push = sigm(scal[1]);
        if (tid < 64) {
            float v = sigm(partial[tid] + partial[64+tid] + partial[128+tid]
                           + partial[192+tid] + b_val[dh*64 + tid]);
            Vb[t*64 + tid] = v;
        }
        if (tid < 128) {   // s update using precomputed scan-1
            float higher = 0.f;
            for (int w2 = wrp + 1; w2 < 4; w2++) higher += wtot[w2];
            float suf = v1 - sv + higher;
            float sn  = fmaxf(sv - fmaxf(pop - suf, 0.f), 0.f);
            if (tid == t) sn = push;
            snewSh[tid] = sn;
        }
        __syncthreads();
        // suffix scan 2 (over s_new)
        float sn2 = 0.f, v2 = 0.f;
        if (tid < 128) {
            sn2 = snewSh[tid]; v2 = sn2;
            #pragma unroll
            for (int off = 1; off < 32; off <<= 1) {
                float tv = __shfl_down_sync(0xffffffffu, v2, off);
                if (lane + off < 32) v2 += tv;
            }
            if (lane == 0) wtot[wrp] = v2;
        }
        __syncthreads();
        if (tid < 128) {
            float higher = 0.f;
            for (int w2 = wrp + 1; w2 < 4; w2++) higher += wtot[w2];
            float suf2 = v2 - sn2 + higher;
            wSh[tid] = fminf(sn2, fmaxf(1.f - suf2, 0.f));
            sSh[tid] = sn2;
        }
        __syncthreads();
        {   // rx half: 64 d x (t+1) i, 4-way i split
            int dl = tid & 63, q = tid >> 6;
            float a = 0.f;
            for (int i = q; i <= t; i += 4) a += wSh[i]*Vb[i*64 + dl];
            partial[tid] = a;
        }
        __syncthreads();
        if (tid < 64)
            g_rx[sb*D_ + dh*64 + tid] = partial[tid] + partial[64+tid]
                                      + partial[128+tid] + partial[192+tid];

        // ---- barrier B arrive (rx complete); wait deferred into gate(t+1) ----
        __syncthreads();
        if (tid == 0) { __threadfence(); atomicAdd(&g_barB, 1u); }
    }
}

// ---------------- output GEMM via tf32 mma.sync, double-buffered ----------------
// Block: 128v x 128t, K=256 in 8 chunks of 32. 8 warps, warp tile 32v x 64t.
// SMEM [k][v]/[k][t] pitch 133, 2 buffers each, LDG(k+1) overlapped with MMA(k).
#define OGBUF 4256   // 32*133
__global__ __launch_bounds__(256)
void out_gemm(const float* __restrict__ W_out, const float* __restrict__ b_out,
              float* __restrict__ out)
{
    extern __shared__ float gsm[];
    float* As  = gsm;                 // 2 x 4256
    float* Bs  = gsm + 2*OGBUF;       // 2 x 4256
    float* bsh = gsm + 4*OGBUF;       // 128

    const int tid  = threadIdx.x;
    const int wid  = tid >> 5, lane = tid & 31;
    const int vbase = blockIdx.x * 128;
    const int b = blockIdx.y;
    const float* hsb = g_hs + (size_t)b * (T_*H_);

    if (tid < 128) {
        int vg = vbase + tid;
        bsh[tid] = (vg < V_) ? b_out[vg] : 0.f;
    }

    const int wv = wid >> 1;        // warp v-tile (0..3)
    const int wt = wid & 1;         // warp t-tile (0..1)
    const int r  = lane >> 2;       // 0..7
    const int cq = lane & 3;        // 0..3

    const int srow = tid >> 3, sf4 = tid & 7;   // staging: 4 reps cover 128 rows

    float acc[2][8][4];
    #pragma unroll
    for (int mi = 0; mi < 2; mi++)
        #pragma unroll
        for (int ni = 0; ni < 8; ni++)
            #pragma unroll
            for (int j = 0; j < 4; j++) acc[mi][ni][j] = 0.f;

    float4 a4[4], b4[4];
    // load chunk 0
    #pragma unroll
    for (int i = 0; i < 4; i++) {
        int row = srow + i*32;
        int vg = vbase + row;
        a4[i] = (vg < V_) ? *(const float4*)&W_out[(size_t)vg*H_ + sf4*4]
                          : make_float4(0.f, 0.f, 0.f, 0.f);
        b4[i] = *(const float4*)&hsb[row*H_ + sf4*4];
    }
    {   // store chunk 0 into buffer 0
        float* Ab = As; float* Bb = Bs;
        #pragma unroll
        for (int i = 0; i < 4; i++) {
            int row = srow + i*32;
            Ab[(sf4*4+0)*133 + row] = tf32r(a4[i].x);
            Ab[(sf4*4+1)*133 + row] = tf32r(a4[i].y);
            Ab[(sf4*4+2)*133 + row] = tf32r(a4[i].z);
            Ab[(sf4*4+3)*133 + row] = tf32r(a4[i].w);
            Bb[(sf4*4+0)*133 + row] = tf32r(b4[i].x);
            Bb[(sf4*4+1)*133 + row] = tf32r(b4[i].y);
            Bb[(sf4*4+2)*133 + row] = tf32r(b4[i].z);
            Bb[(sf4*4+3)*133 + row] = tf32r(b4[i].w);
        }
    }
    __syncthreads();

    for (int kc = 0; kc < 8; kc++) {
        // prefetch chunk kc+1
        if (kc < 7) {
            int k = (kc + 1)*32 + sf4*4;
            #pragma unroll
            for (int i = 0; i < 4; i++) {
                int row = srow + i*32;
                int vg = vbase + row;
                a4[i] = (vg < V_) ? *(const float4*)&W_out[(size_t)vg*H_ + k]
                                  : make_float4(0.f, 0.f, 0.f, 0.f);
                b4[i] = *(const float4*)&hsb[row*H_ + k];
            }
        }
        // compute on buffer kc&1
        const float* Ab = As + (kc & 1)*OGBUF;
        const float* Bb = Bs + (kc & 1)*OGBUF;
        #pragma unroll
        for (int ks = 0; ks < 4; ks++) {
            const int k0 = ks*8;
            uint32_t afr[2][4];
            #pragma unroll
            for (int mi = 0; mi < 2; mi++) {
                int v0 = wv*32 + mi*16;
                afr[mi][0] = __float_as_uint(Ab[(k0+cq  )*133 + v0 + r    ]);
                afr[mi][1] = __float_as_uint(Ab[(k0+cq  )*133 + v0 + r + 8]);
                afr[mi][2] = __float_as_uint(Ab[(k0+cq+4)*133 + v0 + r    ]);
                afr[mi][3] = __float_as_uint(Ab[(k0+cq+4)*133 + v0 + r + 8]);
            }
            #pragma unroll
            for (int ni = 0; ni < 8; ni++) {
                int t0 = wt*64 + ni*8;
                uint32_t bfr[2];
                bfr[0] = __float_as_uint(Bb[(k0+cq  )*133 + t0 + r]);
                bfr[1] = __float_as_uint(Bb[(k0+cq+4)*133 + t0 + r]);
                mma_tf32_16x8x8(acc[0][ni], afr[0], bfr);
                mma_tf32_16x8x8(acc[1][ni], afr[1], bfr);
            }
        }
        // store prefetched chunk into the other buffer
        if (kc < 7) {
            float* An = As + ((kc + 1) & 1)*OGBUF;
            float* Bn = Bs + ((kc + 1) & 1)*OGBUF;
            #pragma unroll
            for (int i = 0; i < 4; i++) {
                int row = srow + i*32;
                An[(sf4*4+0)*133 + row] = tf32r(a4[i].x);
                An[(sf4*4+1)*133 + row] = tf32r(a4[i].y);
                An[(sf4*4+2)*133 + row] = tf32r(a4[i].z);
                An[(sf4*4+3)*133 + row] = tf32r(a4[i].w);
                Bn[(sf4*4+0)*133 + row] = tf32r(b4[i].x);
                Bn[(sf4*4+1)*133 + row] = tf32r(b4[i].y);
                Bn[(sf4*4+2)*133 + row] = tf32r(b4[i].z);
                Bn[(sf4*4+3)*133 + row] = tf32r(b4[i].w);
            }
        }
        __syncthreads();
    }

    // epilogue: c0,c1 -> (v0+r, t0+2cq); c2,c3 -> (v0+r+8, t0+2cq)
    #pragma unroll
    for (int mi = 0; mi < 2; mi++) {
        int vloc0 = wv*32 + mi*16 + r;
        int vloc1 = vloc0 + 8;
        int vg0 = vbase + vloc0, vg1 = vbase + vloc1;
        float bi0 = bsh[vloc0], bi1 = bsh[vloc1];
        #pragma unroll
        for (int ni = 0; ni < 8; ni++) {
            int t0 = wt*64 + ni*8 + 2*cq;
            if (vg0 < V_) {
                float2 o = make_float2(acc[mi][ni][0] + bi0, acc[mi][ni][1] + bi0);
                __stcg((float2*)&out[(size_t)b*((size_t)V_*T_) + (size_t)vg0*T_ + t0], o);
            }
            if (vg1 < V_) {
                float2 o = make_float2(acc[mi][ni][2] + bi1, acc[mi][ni][3] + bi1);
                __stcg((float2*)&out[(size_t)b*((size_t)V_*T_) + (size_t)vg1*T_ + t0], o);
            }
        }
    }
}

// ---------------- launch ----------------
extern "C" void kernel_launch(void* const* d_in, const int* in_sizes, int n_in,
                              void* d_out, int out_size)
{
    const int*   x      = (const int*)  d_in[0];
    const float* emb    = (const float*)d_in[1];
    const float* W_ih   = (const float*)d_in[2];
    const float* b_ih   = (const float*)d_in[3];
    const float* W_hh   = (const float*)d_in[4];
    const float* b_hh   = (const float*)d_in[5];
    const float* W_out  = (const float*)d_in[6];
    const float* b_out  = (const float*)d_in[7];
    const float* W_push = (const float*)d_in[8];
    const float* b_push = (const float*)d_in[9];
    const float* W_pop  = (const float*)d_in[10];
    const float* b_pop  = (const float*)d_in[11];
    const float* W_val  = (const float*)d_in[12];
    const float* b_val  = (const float*)d_in[13];
    float* out = (float*)d_out;

    const size_t R_SMEM = 44200 * sizeof(float);          // ~172.7 KB
    const size_t G_SMEM = (4*OGBUF + 128 + 64) * sizeof(float);  // ~68.9 KB
    static int configured = -1;
    if (configured < 0) {
        cudaFuncSetAttribute(recur_kernel, cudaFuncAttributeMaxDynamicSharedMemorySize,
                             (int)R_SMEM);
        cudaFuncSetAttribute(out_gemm, cudaFuncAttributeMaxDynamicSharedMemorySize,
                             (int)G_SMEM);
        configured = 1;
    }

    setup_kernel<<<64, 256>>>();
    recur_kernel<<<NCTA, NTHR, R_SMEM>>>(x, emb, W_ih, b_ih, W_hh, b_hh,
                                         W_pop, b_pop, W_push, b_push, b_val, W_val);
    dim3 g((V_ + 127) / 128, B_);
    out_gemm<<<g, 256, G_SMEM>>>(W_out, b_out, out);
}

// round 16
// speedup vs baseline: 1.0362x; 1.0362x over previous
#include <cuda_runtime.h>
#include <math.h>
#include <stdint.h>

#define T_   128
#define B_   64
#define E_   128
#define D_   128
#define H_   256
#define V_   8000
#define NCTA 128
#define NTHR 512

// ---------------- persistent device state ----------------
__device__ float g_hx[2][B_*H_];     // double-buffered hidden state
__device__ float g_rx[B_*D_];        // stack read vector
__device__ float g_hs[B_*T_*H_];     // all hidden states, [b][t][h]
__device__ unsigned int g_barA;      // grid barrier A counter (hx ready)
__device__ unsigned int g_barB;      // grid barrier B counter (rx ready)

__device__ __forceinline__ float sigm(float x)   { return 1.0f / (1.0f + __expf(-x)); }
__device__ __forceinline__ float tanh_f(float x) { return 2.0f / (1.0f + __expf(-2.0f*x)) - 1.0f; }
__device__ __forceinline__ float tf32r(float x) {
    float y; asm("cvt.rna.tf32.f32 %0, %1;" : "=f"(y) : "f"(x)); return y;
}

// fp32-accum tf32 tensor-core MMA (sm_80+ portable; compiles for compute_103)
__device__ __forceinline__ void mma_tf32_16x8x8(float* d, const uint32_t* a,
                                                const uint32_t* b) {
    asm volatile(
        "mma.sync.aligned.m16n8k8.row.col.f32.tf32.tf32.f32 "
        "{%0,%1,%2,%3}, {%4,%5,%6,%7}, {%8,%9}, {%0,%1,%2,%3};\n"
        : "+f"(d[0]), "+f"(d[1]), "+f"(d[2]), "+f"(d[3])
        : "r"(a[0]), "r"(a[1]), "r"(a[2]), "r"(a[3]),
          "r"(b[0]), "r"(b[1]));
}

// ---------------- setup ----------------
__global__ void setup_kernel() {
    int tid = blockIdx.x * blockDim.x + threadIdx.x;
    int stride = gridDim.x * blockDim.x;
    if (tid == 0) { g_barA = 0u; g_barB = 0u; }
    for (int i = tid; i < B_*H_; i += stride) g_hx[0][i] = 0.f;
    for (int i = tid; i < B_*D_; i += stride) g_rx[i] = 1.f;
}

// ---------------- persistent recurrence kernel ----------------
// 128 CTAs x 512 thr (16 warps, 4/SMSP for latency hiding), 1 CTA/SM.
// CTA j owns h-units 2j,2j+1 (8 gate rows). Gate GEMM: fp32 FFMA, 4x4
// register tiles, 16-way warp-uniform k-split (8 k's each), single transposed
// chunk buffer, LDG prefetch overlapped with compute.
// Chunk order emb, hx_lo, hx_hi, rx; barrier-B wait deferred to chunk 2;
// barrier-A wait deferred behind emb(t+1) prefetch + suffix-scan-1.
// Stack: CTA c handles batch (c&63), D-half (c>>6). W_valT half in SMEM.
#define WGP  524   // Wg pitch
#define CHP  68    // chunkT pitch [k][b]
#define REDP 544   // red per-kg pitch
__global__ __launch_bounds__(NTHR, 1)
void recur_kernel(const int*   __restrict__ x,     const float* __restrict__ emb,
                  const float* __restrict__ W_ih,  const float* __restrict__ b_ih,
                  const float* __restrict__ W_hh,  const float* __restrict__ b_hh,
                  const float* __restrict__ W_pop, const float* __restrict__ b_pop,
                  const float* __restrict__ W_push,const float* __restrict__ b_push,
                  const float* __restrict__ b_val, const float* __restrict__ W_val)
{
    extern __shared__ float sm[];
    float* Wg      = sm;                    // 8 x 524 = 4192
    float* biasSh  = Wg + 8*WGP;            // 8
    float* chunkT  = biasSh + 8;            // 128 x 68 = 8704  [k][b]
    float* red     = chunkT + 128*CHP;      // 16 x 544 = 8704
    float* gatesSh = red + 16*REDP;         // 512
    float* cxSh    = gatesSh + 512;         // 128
    float* WvT     = cxSh + 128;            // 256 x 65 = 16640
    float* Vb      = WvT + 16640;           // 128 x 64 = 8192
    float* hxSh    = Vb + 8192;             // 256
    float* sSh     = hxSh + 256;            // 128
    float* snewSh  = sSh + 128;             // 128
    float* wSh     = snewSh + 128;          // 128
    float* partial = wSh + 128;             // 512
    float* scal    = partial + 512;         // 2
    float* wtot    = scal + 2;              // 16

    const int tid = threadIdx.x;
    const int cta = blockIdx.x;
    const int h0  = cta * 2;
    const int sb  = cta & 63;    // stack batch
    const int dh  = cta >> 6;    // stack D-half

    // gate weight rows (constant over t), pitch WGP
    for (int idx = tid; idx < 8*512; idx += NTHR) {
        int r = idx >> 9, k = idx & 511;
        int n = (r >> 1) * H_ + h0 + (r & 1);
        Wg[r*WGP + k] = (k < 256) ? W_ih[n*256 + k] : W_hh[n*256 + (k - 256)];
    }
    // W_valT half: WvT[k*65 + dl] = W_val[(dh*64+dl)*H + k]
    for (int idx = tid; idx < 64*256; idx += NTHR) {
        int dl = idx >> 8, k = idx & 255;
        WvT[k*65 + dl] = W_val[(dh*64 + dl)*H_ + k];
    }
    if (tid < 8) {
        int n = (tid >> 1) * H_ + h0 + (tid & 1);
        biasSh[tid] = b_ih[n] + b_hh[n];
    }
    if (tid < 128) { cxSh[tid] = 0.f; sSh[tid] = 0.f; }
    __syncthreads();

    // staging role: batch sbt, k-eighth kq8 (16 k's per chunk)
    const int sbt = tid & 63, kq8 = tid >> 6;
    const int lane = tid & 31, wrp = tid >> 5;
    // compute role: warp-uniform k-slice kg (8 k's), cell group (ng, bg)
    const int kg = wrp;                 // 0..15
    const int ng = lane >> 4;           // 0..1 -> 4 rows each
    const int bg = lane & 15;           // 0..15 -> 4 batches each

    // prefetch emb chunk for t=0
    float4 st[4];
    int tok = x[sbt];
    {
        const float4* s = (const float4*)(emb + (size_t)tok*E_ + kq8*16);
        #pragma unroll
        for (int j = 0; j < 4; j++) st[j] = s[j];
    }

    for (int t = 0; t < T_; t++) {
        const int cur = t & 1, nxt = cur ^ 1;

        // ---------- gate phase: gates = [ex, hx_lo, hx_hi, rx] @ Wg^T ----------
        float acc[4][4];
        #pragma unroll
        for (int i = 0; i < 4; i++)
            #pragma unroll
            for (int j = 0; j < 4; j++) acc[i][j] = 0.f;

        for (int kc = 0; kc < 4; kc++) {
            // weight-column offset for this chunk: emb, hx_lo, hx_hi, rx
            const int woff = (kc == 0) ? 0 : (kc == 1) ? 256 : (kc == 2) ? 384 : 128;

            // store staged regs transposed into chunkT[k][b]
            #pragma unroll
            for (int j = 0; j < 4; j++) {
                int k = kq8*16 + j*4;
                float* c = chunkT + k*CHP + sbt;
                c[0*CHP] = st[j].x;
                c[1*CHP] = st[j].y;
                c[2*CHP] = st[j].z;
                c[3*CHP] = st[j].w;
            }
            __syncthreads();
            // deferred barrier-B wait: rx(t-1) must be published before we
            // prefetch it (chunk 3). ~2 chunks of compute already hid the wait.
            if (kc == 2) {
                if (tid == 0) {
                    while (*((volatile unsigned int*)&g_barB) <
                           (unsigned int)t*NCTA) { }
                    __threadfence();   // invalidate L1 so rx loads see L2
                }
                __syncthreads();
            }
            // prefetch next chunk while computing this one
            if (kc < 3) {
                const float4* s = (kc == 0)
                    ? (const float4*)(g_hx[cur] + sbt*H_ + kq8*16)
                    : (kc == 1)
                    ? (const float4*)(g_hx[cur] + sbt*H_ + 128 + kq8*16)
                    : (const float4*)(g_rx + sbt*D_ + kq8*16);
                #pragma unroll
                for (int j = 0; j < 4; j++) st[j] = s[j];
            }
            // compute: 4 rows x 4 batches per thread over 8 k's
            const float* wb = Wg + (ng*4)*WGP + woff + kg*8;
            const float* cb = chunkT + (kg*8)*CHP + bg*4;
            #pragma unroll
            for (int kk = 0; kk < 2; kk++) {
                float4 wv[4], cv[4];
                #pragma unroll
                for (int i = 0; i < 4; i++)
                    wv[i] = *(const float4*)(wb + i*WGP + kk*4);
                #pragma unroll
                for (int k2 = 0; k2 < 4; k2++)
                    cv[k2] = *(const float4*)(cb + (kk*4 + k2)*CHP);
                #pragma unroll
                for (int i = 0; i < 4; i++) {
                    float ws[4] = {wv[i].x, wv[i].y, wv[i].z, wv[i].w};
                    #pragma unroll
                    for (int k2 = 0; k2 < 4; k2++) {
                        acc[i][0] += ws[k2]*cv[k2].x;
                        acc[i][1] += ws[k2]*cv[k2].y;
                        acc[i][2] += ws[k2]*cv[k2].z;
                        acc[i][3] += ws[k2]*cv[k2].w;
                    }
                }
            }
            if (kc < 3) __syncthreads();   // protect chunkT overwrite
        }
        // k-split reduction: 16 partial slices
        #pragma unroll
        for (int i = 0; i < 4; i++) {
            int n = ng*4 + i;
            *(float4*)&red[kg*REDP + n*CHP + bg*4] =
                make_float4(acc[i][0], acc[i][1], acc[i][2], acc[i][3]);
        }
        __syncthreads();
        {
            int n = tid >> 6, b = tid & 63;
            float s = biasSh[n];
            #pragma unroll
            for (int kg2 = 0; kg2 < 16; kg2++) s += red[kg2*REDP + n*CHP + b];
            gatesSh[tid] = s;
        }
        __syncthreads();
        if (tid < 128) {
            int hl = tid >> 6, b = tid & 63;
            float ig = gatesSh[(0 + hl)*64 + b];
            float fg = gatesSh[(2 + hl)*64 + b];
            float gg = gatesSh[(4 + hl)*64 + b];
            float og = gatesSh[(6 + hl)*64 + b];
            int h = h0 + hl;
            float c  = sigm(fg)*cxSh[tid] + sigm(ig)*tanh_f(gg);
            float hv = sigm(og)*tanh_f(c);
            cxSh[tid] = c;
            g_hx[nxt][b*H_ + h] = hv;
            g_hs[b*(T_*H_) + t*H_ + h] = hv;
        }

        if (t == T_ - 1) break;   // rx(127)/s(127) dead; g_hs visible at kernel end

        // ---- barrier A arrive (hx complete) ----
        __syncthreads();
        if (tid == 0) { __threadfence(); atomicAdd(&g_barA, 1u); }

        // hidden work while other CTAs arrive:
        // (1) emb(t+1) prefetch (input-only data)
        tok = x[(t+1)*B_ + sbt];
        {
            const float4* s = (const float4*)(emb + (size_t)tok*E_ + kq8*16);
            #pragma unroll
            for (int j = 0; j < 4; j++) st[j] = s[j];
        }
        // (2) suffix scan 1 over s (CTA-local state from step t-1)
        float sv = 0.f, v1 = 0.f;
        if (tid < 128) {
            sv = sSh[tid]; v1 = sv;
            #pragma unroll
            for (int off = 1; off < 32; off <<= 1) {
                float tv = __shfl_down_sync(0xffffffffu, v1, off);
                if (lane + off < 32) v1 += tv;
            }
            if (lane == 0) wtot[wrp] = v1;
        }

        // ---- barrier A wait ----
        if (tid == 0) {
            while (*((volatile unsigned int*)&g_barA) <
                   (unsigned int)(t + 1)*NCTA) { }
            __threadfence();   // invalidate L1 so hx loads see L2
        }
        __syncthreads();

        // ---------- stack phase (all 128 CTAs; 2 per batch) ----------
        if (tid < 256) hxSh[tid] = g_hx[nxt][sb*H_ + tid];
        __syncthreads();
        {   // vals matvec: 64 outputs x 256 K, 8-way K split
            int dl = tid & 63, q = tid >> 6;          // q 0..7, 32 k's each
            const float* wcol = WvT + q*32*65 + dl;
            const float* hq   = hxSh + q*32;
            float a = 0.f;
            #pragma unroll 8
            for (int k = 0; k < 32; k++) a += wcol[k*65] * hq[k];
            partial[tid] = a;
        }
        if (wrp == 6 || wrp == 7) {   // pop / push dots
            const float* wrow = (wrp == 6) ? W_pop : W_push;
            float a = 0.f;
            for (int k = lane; k < H_; k += 32) a += wrow[k]*hxSh[k];
            #pragma unroll
            for (int off = 16; off > 0; off >>= 1)
                a += __shfl_xor_sync(0xffffffffu, a, off);
            if (lane == 0) scal[wrp - 6] = a + ((wrp == 6) ? b_pop[0] : b_push[0]);
        }
        __syncthreads();
        float pop  = sigm(scal[0]);
        float push = sigm(scal[1]);
        if (tid < 64) {
            float v = partial[tid] + partial[64+tid] + partial[128+tid]
                    + partial[192+tid] + partial[256+tid] + partial[320+tid]
                    + partial[384+tid] + partial[448+tid];
            Vb[t*64 + tid] = sigm(v + b_val[dh*64 + tid]);
        }
        if (tid < 128) {   // s update using precomputed scan-1
            float higher = 0.f;
            for (int w2 = wrp + 1; w2 < 4; w2++) higher += wtot[w2];
            float suf = v1 - sv + higher;
            float sn  = fmaxf(sv - fmaxf(pop - suf, 0.f), 0.f);
            if (tid == t) sn = push;
            snewSh[tid] = sn;
        }
        __syncthreads();
        // suffix scan 2 (over s_new)
        float sn2 = 0.f, v2 = 0.f;
        if (tid < 128) {
            sn2 = snewSh[tid]; v2 = sn2;
            #pragma unroll
            for (int off = 1; off < 32; off <<= 1) {
                float tv = __shfl_down_sync(0xffffffffu, v2, off);
                if (lane + off < 32) v2 += tv;
            }
            if (lane == 0) wtot[wrp] = v2;
        }
        __syncthreads();
        if (tid < 128) {
            float higher = 0.f;
            for (int w2 = wrp + 1; w2 < 4; w2++) higher += wtot[w2];
            float suf2 = v2 - sn2 + higher;
            wSh[tid] = fminf(sn2, fmaxf(1.f - suf2, 0.f));
            sSh[tid] = sn2;
        }
        __syncthreads();
        {   // rx half: 64 d x (t+1) i, 8-way i split
            int dl = tid & 63, q = tid >> 6;
            float a = 0.f;
            for (int i = q; i <= t; i += 8) a += wSh[i]*Vb[i*64 + dl];
            partial[tid] = a;
        }
        __syncthreads();
        if (tid < 64)
            g_rx[sb*D_ + dh*64 + tid] =
                  partial[tid]     + partial[64+tid]  + partial[128+tid]
                + partial[192+tid] + partial[256+tid] + partial[320+tid]
                + partial[384+tid] + partial[448+tid];

        // ---- barrier B arrive (rx complete); wait deferred into gate(t+1) ----
        __syncthreads();
        if (tid == 0) { __threadfence(); atomicAdd(&g_barB, 1u); }
    }
}

// ---------------- output GEMM via tf32 mma.sync, double-buffered ----------------
// Block: 128v x 128t, K=256 in 8 chunks of 32. 8 warps, warp tile 32v x 64t.
// SMEM [k][v]/[k][t] pitch 133, 2 buffers each, LDG(k+1) overlapped with MMA(k).
#define OGBUF 4256   // 32*133
__global__ __launch_bounds__(256)
void out_gemm(const float* __restrict__ W_out, const float* __restrict__ b_out,
              float* __restrict__ out)
{
    extern __shared__ float gsm[];
    float* As  = gsm;                 // 2 x 4256
    float* Bs  = gsm + 2*OGBUF;       // 2 x 4256
    float* bsh = gsm + 4*OGBUF;       // 128

    const int tid  = threadIdx.x;
    const int wid  = tid >> 5, lane = tid & 31;
    const int vbase = blockIdx.x * 128;
    const int b = blockIdx.y;
    const float* hsb = g_hs + (size_t)b * (T_*H_);

    if (tid < 128) {
        int vg = vbase + tid;
        bsh[tid] = (vg < V_) ? b_out[vg] : 0.f;
    }

    const int wv = wid >> 1;        // warp v-tile (0..3)
    const int wt = wid & 1;         // warp t-tile (0..1)
    const int r  = lane >> 2;       // 0..7
    const int cq = lane & 3;        // 0..3

    const int srow = tid >> 3, sf4 = tid & 7;   // staging: 4 reps cover 128 rows

    float acc[2][8][4];
    #pragma unroll
    for (int mi = 0; mi < 2; mi++)
        #pragma unroll
        for (int ni = 0; ni < 8; ni++)
            #pragma unroll
            for (int j = 0; j < 4; j++) acc[mi][ni][j] = 0.f;

    float4 a4[4], b4[4];
    // load chunk 0
    #pragma unroll
    for (int i = 0; i < 4; i++) {
        int row = srow + i*32;
        int vg = vbase + row;
        a4[i] = (vg < V_) ? *(const float4*)&W_out[(size_t)vg*H_ + sf4*4]
                          : make_float4(0.f, 0.f, 0.f, 0.f);
        b4[i] = *(const float4*)&hsb[row*H_ + sf4*4];
    }
    {   // store chunk 0 into buffer 0
        float* Ab = As; float* Bb = Bs;
        #pragma unroll
        for (int i = 0; i < 4; i++) {
            int row = srow + i*32;
            Ab[(sf4*4+0)*133 + row] = tf32r(a4[i].x);
            Ab[(sf4*4+1)*133 + row] = tf32r(a4[i].y);
            Ab[(sf4*4+2)*133 + row] = tf32r(a4[i].z);
            Ab[(sf4*4+3)*133 + row] = tf32r(a4[i].w);
            Bb[(sf4*4+0)*133 + row] = tf32r(b4[i].x);
            Bb[(sf4*4+1)*133 + row] = tf32r(b4[i].y);
            Bb[(sf4*4+2)*133 + row] = tf32r(b4[i].z);
            Bb[(sf4*4+3)*133 + row] = tf32r(b4[i].w);
        }
    }
    __syncthreads();

    for (int kc = 0; kc < 8; kc++) {
        // prefetch chunk kc+1
        if (kc < 7) {
            int k = (kc + 1)*32 + sf4*4;
            #pragma unroll
            for (int i = 0; i < 4; i++) {
                int row = srow + i*32;
                int vg = vbase + row;
                a4[i] = (vg < V_) ? *(const float4*)&W_out[(size_t)vg*H_ + k]
                                  : make_float4(0.f, 0.f, 0.f, 0.f);
                b4[i] = *(const float4*)&hsb[row*H_ + k];
            }
        }
        // compute on buffer kc&1
        const float* Ab = As + (kc & 1)*OGBUF;
        const float* Bb = Bs + (kc & 1)*OGBUF;
        #pragma unroll
        for (int ks = 0; ks < 4; ks++) {
            const int k0 = ks*8;
            uint32_t afr[2][4];
            #pragma unroll
            for (int mi = 0; mi < 2; mi++) {
                int v0 = wv*32 + mi*16;
                afr[mi][0] = __float_as_uint(Ab[(k0+cq  )*133 + v0 + r    ]);
                afr[mi][1] = __float_as_uint(Ab[(k0+cq  )*133 + v0 + r + 8]);
                afr[mi][2] = __float_as_uint(Ab[(k0+cq+4)*133 + v0 + r    ]);
                afr[mi][3] = __float_as_uint(Ab[(k0+cq+4)*133 + v0 + r + 8]);
            }
            #pragma unroll
            for (int ni = 0; ni < 8; ni++) {
                int t0 = wt*64 + ni*8;
                uint32_t bfr[2];
                bfr[0] = __float_as_uint(Bb[(k0+cq  )*133 + t0 + r]);
                bfr[1] = __float_as_uint(Bb[(k0+cq+4)*133 + t0 + r]);
                mma_tf32_16x8x8(acc[0][ni], afr[0], bfr);
                mma_tf32_16x8x8(acc[1][ni], afr[1], bfr);
            }
        }
        // store prefetched chunk into the other buffer
        if (kc < 7) {
            float* An = As + ((kc + 1) & 1)*OGBUF;
            float* Bn = Bs + ((kc + 1) & 1)*OGBUF;
            #pragma unroll
            for (int i = 0; i < 4; i++) {
                int row = srow + i*32;
                An[(sf4*4+0)*133 + row] = tf32r(a4[i].x);
                An[(sf4*4+1)*133 + row] = tf32r(a4[i].y);
                An[(sf4*4+2)*133 + row] = tf32r(a4[i].z);
                An[(sf4*4+3)*133 + row] = tf32r(a4[i].w);
                Bn[(sf4*4+0)*133 + row] = tf32r(b4[i].x);
                Bn[(sf4*4+1)*133 + row] = tf32r(b4[i].y);
                Bn[(sf4*4+2)*133 + row] = tf32r(b4[i].z);
                Bn[(sf4*4+3)*133 + row] = tf32r(b4[i].w);
            }
        }
        __syncthreads();
    }

    // epilogue: c0,c1 -> (v0+r, t0+2cq); c2,c3 -> (v0+r+8, t0+2cq)
    #pragma unroll
    for (int mi = 0; mi < 2; mi++) {
        int vloc0 = wv*32 + mi*16 + r;
        int vloc1 = vloc0 + 8;
        int vg0 = vbase + vloc0, vg1 = vbase + vloc1;
        float bi0 = bsh[vloc0], bi1 = bsh[vloc1];
        #pragma unroll
        for (int ni = 0; ni < 8; ni++) {
            int t0 = wt*64 + ni*8 + 2*cq;
            if (vg0 < V_) {
                float2 o = make_float2(acc[mi][ni][0] + bi0, acc[mi][ni][1] + bi0);
                __stcg((float2*)&out[(size_t)b*((size_t)V_*T_) + (size_t)vg0*T_ + t0], o);
            }
            if (vg1 < V_) {
                float2 o = make_float2(acc[mi][ni][2] + bi1, acc[mi][ni][3] + bi1);
                __stcg((float2*)&out[(size_t)b*((size_t)V_*T_) + (size_t)vg1*T_ + t0], o);
            }
        }
    }
}

// ---------------- launch ----------------
extern "C" void kernel_launch(void* const* d_in, const int* in_sizes, int n_in,
                              void* d_out, int out_size)
{
    const int*   x      = (const int*)  d_in[0];
    const float* emb    = (const float*)d_in[1];
    const float* W_ih   = (const float*)d_in[2];
    const float* b_ih   = (const float*)d_in[3];
    const float* W_hh   = (const float*)d_in[4];
    const float* b_hh   = (const float*)d_in[5];
    const float* W_out  = (const float*)d_in[6];
    const float* b_out  = (const float*)d_in[7];
    const float* W_push = (const float*)d_in[8];
    const float* b_push = (const float*)d_in[9];
    const float* W_pop  = (const float*)d_in[10];
    const float* b_pop  = (const float*)d_in[11];
    const float* W_val  = (const float*)d_in[12];
    const float* b_val  = (const float*)d_in[13];
    float* out = (float*)d_out;

    const size_t R_SMEM = 48260 * sizeof(float);          // ~188.5 KB
    const size_t G_SMEM = (4*OGBUF + 128 + 64) * sizeof(float);  // ~68.9 KB
    static int configured = -1;
    if (configured < 0) {
        cudaFuncSetAttribute(recur_kernel, cudaFuncAttributeMaxDynamicSharedMemorySize,
                             (int)R_SMEM);
        cudaFuncSetAttribute(out_gemm, cudaFuncAttributeMaxDynamicSharedMemorySize,
                             (int)G_SMEM);
        configured = 1;
    }

    setup_kernel<<<64, 256>>>();
    recur_kernel<<<NCTA, NTHR, R_SMEM>>>(x, emb, W_ih, b_ih, W_hh, b_hh,
                                         W_pop, b_pop, W_push, b_push, b_val, W_val);
    dim3 g((V_ + 127) / 128, B_);
    out_gemm<<<g, 256, G_SMEM>>>(W_out, b_out, out);
}

// round 17
// speedup vs baseline: 1.3256x; 1.2793x over previous
#include <cuda_runtime.h>
#include <math.h>
#include <stdint.h>

#define T_   128
#define B_   64
#define E_   128
#define D_   128
#define H_   256
#define V_   8000
#define NCTA 128
#define NTHR 256

// ---------------- persistent device state ----------------
__device__ float g_hx[2][B_*H_];     // double-buffered hidden state
__device__ float g_rx[B_*D_];        // stack read vector
__device__ float g_hs[B_*T_*H_];     // all hidden states, [b][t][h]
__device__ unsigned int g_barA;      // grid barrier A counter (hx ready)
__device__ unsigned int g_barB;      // grid barrier B counter (rx ready)

__device__ __forceinline__ float sigm(float x)   { return 1.0f / (1.0f + __expf(-x)); }
__device__ __forceinline__ float tanh_f(float x) { return 2.0f / (1.0f + __expf(-2.0f*x)) - 1.0f; }
__device__ __forceinline__ float tf32r(float x) {
    float y; asm("cvt.rna.tf32.f32 %0, %1;" : "=f"(y) : "f"(x)); return y;
}

// fp32-accum tf32 tensor-core MMA (sm_80+ portable; compiles for compute_103)
__device__ __forceinline__ void mma_tf32_16x8x8(float* d, const uint32_t* a,
                                                const uint32_t* b) {
    asm volatile(
        "mma.sync.aligned.m16n8k8.row.col.f32.tf32.tf32.f32 "
        "{%0,%1,%2,%3}, {%4,%5,%6,%7}, {%8,%9}, {%0,%1,%2,%3};\n"
        : "+f"(d[0]), "+f"(d[1]), "+f"(d[2]), "+f"(d[3])
        : "r"(a[0]), "r"(a[1]), "r"(a[2]), "r"(a[3]),
          "r"(b[0]), "r"(b[1]));
}

// ---------------- setup ----------------
__global__ void setup_kernel() {
    int tid = blockIdx.x * blockDim.x + threadIdx.x;
    int stride = gridDim.x * blockDim.x;
    if (tid == 0) { g_barA = 0u; g_barB = 0u; }
    for (int i = tid; i < B_*H_; i += stride) g_hx[0][i] = 0.f;
    for (int i = tid; i < B_*D_; i += stride) g_rx[i] = 1.f;
}

// ---------------- persistent recurrence kernel ----------------
// 128 CTAs x 256 thr, 1 CTA/SM. Gate tiling: cta = ng2*4 + bg2 with
// ng2 = cta>>2 (h-units [ng2*8, +8), all 4 gates -> 32 weight rows in SMEM)
// and bg2 = cta&3 (batches [bg2*16, +16)). Each CTA stages only its 16
// batches (32 KB/step vs 131 KB/step before -> 4x less chip L2 traffic).
// Pointwise LSTM update is CTA-local (owns all 4 gates for its (h,b) block).
// Chunk order emb, hx_lo, hx_hi, rx; barrier-B wait deferred to chunk 2;
// barrier-A wait deferred behind emb(t+1) prefetch + suffix-scan-1.
// Stack: CTA c handles batch (c&63), D-half (c>>6). W_valT half in SMEM.
#define WGP  524   // Wg pitch
#define CHP  20    // chunkT pitch [k][b] (16 batches + pad, 16B-aligned)
#define REDP 640   // red per-kg pitch (32 n x 20)
__global__ __launch_bounds__(NTHR, 1)
void recur_kernel(const int*   __restrict__ x,     const float* __restrict__ emb,
                  const float* __restrict__ W_ih,  const float* __restrict__ b_ih,
                  const float* __restrict__ W_hh,  const float* __restrict__ b_hh,
                  const float* __restrict__ W_pop, const float* __restrict__ b_pop,
                  const float* __restrict__ W_push,const float* __restrict__ b_push,
                  const float* __restrict__ b_val, const float* __restrict__ W_val)
{
    extern __shared__ float sm[];
    float* Wg      = sm;                    // 32 x 524 = 16768
    float* biasSh  = Wg + 32*WGP;           // 32
    float* chunkT  = biasSh + 32;           // 128 x 20 = 2560  [k][b]
    float* red     = chunkT + 128*CHP;      // 8 x 640 = 5120
    float* gatesSh = red + 8*REDP;          // 512 (32 n x 16 b)
    float* cxSh    = gatesSh + 512;         // 128
    float* WvT     = cxSh + 128;            // 256 x 65 = 16640
    float* Vb      = WvT + 16640;           // 128 x 64 = 8192
    float* hxSh    = Vb + 8192;             // 256
    float* sSh     = hxSh + 256;            // 128
    float* snewSh  = sSh + 128;             // 128
    float* wSh     = snewSh + 128;          // 128
    float* partial = wSh + 128;             // 256
    float* scal    = partial + 256;         // 2
    float* wtot    = scal + 2;              // 8

    const int tid = threadIdx.x;
    const int cta = blockIdx.x;
    const int ng2 = cta >> 2;    // h-group (0..31): h-units [ng2*8, +8)
    const int bg2 = cta & 3;     // batch-group (0..3): batches [bg2*16, +16)
    const int sb  = cta & 63;    // stack batch
    const int dh  = cta >> 6;    // stack D-half

    // gate weight rows (constant over t): r = g*8+hl -> n = g*256 + ng2*8 + hl
    for (int idx = tid; idx < 32*512; idx += NTHR) {
        int r = idx >> 9, k = idx & 511;
        int n = (r >> 3) * H_ + ng2*8 + (r & 7);
        Wg[r*WGP + k] = (k < 256) ? W_ih[n*256 + k] : W_hh[n*256 + (k - 256)];
    }
    // W_valT half: WvT[k*65 + dl] = W_val[(dh*64+dl)*H + k]
    for (int idx = tid; idx < 64*256; idx += NTHR) {
        int dl = idx >> 8, k = idx & 255;
        WvT[k*65 + dl] = W_val[(dh*64 + dl)*H_ + k];
    }
    if (tid < 32) {
        int n = (tid >> 3) * H_ + ng2*8 + (tid & 7);
        biasSh[tid] = b_ih[n] + b_hh[n];
    }
    if (tid < 128) { cxSh[tid] = 0.f; sSh[tid] = 0.f; }
    __syncthreads();

    // staging role: batch-local bl (0..15), k-slice kq16 (8 k's per chunk)
    const int bl = tid & 15, kq16 = tid >> 4;
    const int gb = bg2*16 + bl;              // global batch for staging
    const int lane = tid & 31, wrp = tid >> 5;
    // compute role: warp k-slice kg (16 k's/chunk), lane -> (nt, bt)
    const int kg = wrp;                      // 0..7
    const int nt = lane >> 2;                // 0..7 -> rows nt*4..+3 (of 32)
    const int bt = lane & 3;                 // 0..3 -> batches bt*4..+3 (of 16)

    // prefetch emb chunk for t=0
    float4 st[2];
    int tok = x[gb];
    {
        const float4* s = (const float4*)(emb + (size_t)tok*E_ + kq16*8);
        st[0] = s[0]; st[1] = s[1];
    }

    for (int t = 0; t < T_; t++) {
        const int cur = t & 1, nxt = cur ^ 1;

        // ---------- gate phase: gates = [ex, hx_lo, hx_hi, rx] @ Wg^T ----------
        float acc[4][4];
        #pragma unroll
        for (int i = 0; i < 4; i++)
            #pragma unroll
            for (int j = 0; j < 4; j++) acc[i][j] = 0.f;

        for (int kc = 0; kc < 4; kc++) {
            // weight-column offset for this chunk: emb, hx_lo, hx_hi, rx
            const int woff = (kc == 0) ? 0 : (kc == 1) ? 256 : (kc == 2) ? 384 : 128;

            // store staged regs transposed into chunkT[k][b]
            #pragma unroll
            for (int j = 0; j < 2; j++) {
                int k = kq16*8 + j*4;
                float* c = chunkT + k*CHP + bl;
                c[0*CHP] = st[j].x;
                c[1*CHP] = st[j].y;
                c[2*CHP] = st[j].z;
                c[3*CHP] = st[j].w;
            }
            __syncthreads();
            // deferred barrier-B wait: rx(t-1) must be published before we
            // prefetch it (chunk 3). ~2 chunks of compute already hid the wait.
            if (kc == 2) {
                if (tid == 0) {
                    while (*((volatile unsigned int*)&g_barB) <
                           (unsigned int)t*NCTA) { }
                    __threadfence();   // invalidate L1 so rx loads see L2
                }
                __syncthreads();
            }
            // prefetch next chunk while computing this one
            if (kc < 3) {
                const float4* s = (kc == 0)
                    ? (const float4*)(g_hx[cur] + gb*H_ + kq16*8)
                    : (kc == 1)
                    ? (const float4*)(g_hx[cur] + gb*H_ + 128 + kq16*8)
                    : (const float4*)(g_rx + gb*D_ + kq16*8);
                st[0] = s[0]; st[1] = s[1];
            }
            // compute: 4 rows x 4 batches per thread over 16 k's
            const float* wb = Wg + (nt*4)*WGP + woff + kg*16;
            const float* cb = chunkT + (kg*16)*CHP + bt*4;
            #pragma unroll
            for (int kk = 0; kk < 4; kk++) {
                float4 wv[4], cv[4];
                #pragma unroll
                for (int i = 0; i < 4; i++)
                    wv[i] = *(const float4*)(wb + i*WGP + kk*4);
                #pragma unroll
                for (int k2 = 0; k2 < 4; k2++)
                    cv[k2] = *(const float4*)(cb + (kk*4 + k2)*CHP);
                #pragma unroll
                for (int i = 0; i < 4; i++) {
                    float ws[4] = {wv[i].x, wv[i].y, wv[i].z, wv[i].w};
                    #pragma unroll
                    for (int k2 = 0; k2 < 4; k2++) {
                        acc[i][0] += ws[k2]*cv[k2].x;
                        acc[i][1] += ws[k2]*cv[k2].y;
                        acc[i][2] += ws[k2]*cv[k2].z;
                        acc[i][3] += ws[k2]*cv[k2].w;
                    }
                }
            }
            if (kc < 3) __syncthreads();   // protect chunkT overwrite
        }
        // k-split reduction: 8 partial slices
        #pragma unroll
        for (int i = 0; i < 4; i++) {
            int n = nt*4 + i;
            *(float4*)&red[kg*REDP + n*CHP + bt*4] =
                make_float4(acc[i][0], acc[i][1], acc[i][2], acc[i][3]);
        }
        __syncthreads();
        #pragma unroll
        for (int rep = 0; rep < 2; rep++) {
            int cell = tid + rep*256;
            int n = cell >> 4, b = cell & 15;
            float s = biasSh[n];
            #pragma unroll
            for (int kg2 = 0; kg2 < 8; kg2++) s += red[kg2*REDP + n*CHP + b];
            gatesSh[n*16 + b] = s;
        }
        __syncthreads();
        if (tid < 128) {
            int hl = tid >> 4, b = tid & 15;
            float ig = gatesSh[(0*8 + hl)*16 + b];
            float fg = gatesSh[(1*8 + hl)*16 + b];
            float gg = gatesSh[(2*8 + hl)*16 + b];
            float og = gatesSh[(3*8 + hl)*16 + b];
            int hg = ng2*8 + hl;
            int bglob = bg2*16 + b;
            float c  = sigm(fg)*cxSh[tid] + sigm(ig)*tanh_f(gg);
            float hv = sigm(og)*tanh_f(c);
            cxSh[tid] = c;
            g_hx[nxt][bglob*H_ + hg] = hv;
            g_hs[bglob*(T_*H_) + t*H_ + hg] = hv;
        }

        if (t == T_ - 1) break;   // rx(127)/s(127) dead; g_hs visible at kernel end

        // ---- barrier A arrive (hx complete) ----
        __syncthreads();
        if (tid == 0) { __threadfence(); atomicAdd(&g_barA, 1u); }

        // hidden work while other CTAs arrive:
        // (1) emb(t+1) prefetch (input-only data)
        tok = x[(t+1)*B_ + gb];
        {
            const float4* s = (const float4*)(emb + (size_t)tok*E_ + kq16*8);
            st[0] = s[0]; st[1] = s[1];
        }
        // (2) suffix scan 1 over s (CTA-local state from step t-1)
        float sv = 0.f, v1 = 0.f;
        if (tid < 128) {
            sv = sSh[tid]; v1 = sv;
            #pragma unroll
            for (int off = 1; off < 32; off <<= 1) {
                float tv = __shfl_down_sync(0xffffffffu, v1, off);
                if (lane + off < 32) v1 += tv;
            }
            if (lane == 0) wtot[wrp] = v1;
        }

        // ---- barrier A wait ----
        if (tid == 0) {
            while (*((volatile unsigned int*)&g_barA) <
                   (unsigned int)(t + 1)*NCTA) { }
            __threadfence();   // invalidate L1 so hx loads see L2
        }
        __syncthreads();

        // ---------- stack phase (all 128 CTAs; 2 per batch) ----------
        hxSh[tid] = g_hx[nxt][sb*H_ + tid];
        __syncthreads();
        {   // vals matvec: 64 outputs x 256 K, 4-way K split
            int dl = tid & 63, q = tid >> 6;
            const float* wcol = WvT + q*64*65 + dl;
            const float* hq   = hxSh + q*64;
            float a = 0.f;
            #pragma unroll 8
            for (int k = 0; k < 64; k++) a += wcol[k*65] * hq[k];
            partial[tid] = a;
        }
        if (wrp == 6 || wrp == 7) {   // pop / push dots
            const float* wrow = (wrp == 6) ? W_pop : W_push;
            float a = 0.f;
            for (int k = lane; k < H_; k += 32) a += wrow[k]*hxSh[k];
            #pragma unroll
            for (int off = 16; off > 0; off >>= 1)
                a += __shfl_xor_sync(0xffffffffu, a, off);
            if (lane == 0) scal[wrp - 6] = a + ((wrp == 6) ? b_pop[0] : b_push[0]);
        }
        __syncthreads();
        float pop  = sigm(scal[0]);
        float push = sigm(scal[1]);
        if (tid < 64) {
            float v = sigm(partial[tid] + partial[64+tid] + partial[128+tid]
                           + partial[192+tid] + b_val[dh*64 + tid]);
            Vb[t*64 + tid] = v;
        }
        if (tid < 128) {   // s update using precomputed scan-1
            float higher = 0.f;
            for (int w2 = wrp + 1; w2 < 4; w2++) higher += wtot[w2];
            float suf = v1 - sv + higher;
            float sn  = fmaxf(sv - fmaxf(pop - suf, 0.f), 0.f);
            if (tid == t) sn = push;
            snewSh[tid] = sn;
        }
        __syncthreads();
        // suffix scan 2 (over s_new)
        float sn2 = 0.f, v2 = 0.f;
        if (tid < 128) {
            sn2 = snewSh[tid]; v2 = sn2;
            #pragma unroll
            for (int off = 1; off < 32; off <<= 1) {
                float tv = __shfl_down_sync(0xffffffffu, v2, off);
                if (lane + off < 32) v2 += tv;
            }
            if (lane == 0) wtot[wrp] = v2;
        }
        __syncthreads();
        if (tid < 128) {
            float higher = 0.f;
            for (int w2 = wrp + 1; w2 < 4; w2++) higher += wtot[w2];
            float suf2 = v2 - sn2 + higher;
            wSh[tid] = fminf(sn2, fmaxf(1.f - suf2, 0.f));
            sSh[tid] = sn2;
        }
        __syncthreads();
        {   // rx half: 64 d x (t+1) i, 4-way i split
            int dl = tid & 63, q = tid >> 6;
            float a = 0.f;
            for (int i = q; i <= t; i += 4) a += wSh[i]*Vb[i*64 + dl];
            partial[tid] = a;
        }
        __syncthreads();
        if (tid < 64)
            g_rx[sb*D_ + dh*64 + tid] = partial[tid] + partial[64+tid]
                                      + partial[128+tid] + partial[192+tid];

        // ---- barrier B arrive (rx complete); wait deferred into gate(t+1) ----
        __syncthreads();
        if (tid == 0) { __threadfence(); atomicAdd(&g_barB, 1u); }
    }
}

// ---------------- output GEMM via tf32 mma.sync, double-buffered ----------------
// Block: 128v x 128t, K=256 in 8 chunks of 32. 8 warps, warp tile 32v x 64t.
// SMEM [k][v]/[k][t] pitch 133, 2 buffers each, LDG(k+1) overlapped with MMA(k).
#define OGBUF 4256   // 32*133
__global__ __launch_bounds__(256)
void out_gemm(const float* __restrict__ W_out, const float* __restrict__ b_out,
              float* __restrict__ out)
{
    extern __shared__ float gsm[];
    float* As  = gsm;                 // 2 x 4256
    float* Bs  = gsm + 2*OGBUF;       // 2 x 4256
    float* bsh = gsm + 4*OGBUF;       // 128

    const int tid  = threadIdx.x;
    const int wid  = tid >> 5, lane = tid & 31;
    const int vbase = blockIdx.x * 128;
    const int b = blockIdx.y;
    const float* hsb = g_hs + (size_t)b * (T_*H_);

    if (tid < 128) {
        int vg = vbase + tid;
        bsh[tid] = (vg < V_) ? b_out[vg] : 0.f;
    }

    const int wv = wid >> 1;        // warp v-tile (0..3)
    const int wt = wid & 1;         // warp t-tile (0..1)
    const int r  = lane >> 2;       // 0..7
    const int cq = lane & 3;        // 0..3

    const int srow = tid >> 3, sf4 = tid & 7;   // staging: 4 reps cover 128 rows

    float acc[2][8][4];
    #pragma unroll
    for (int mi = 0; mi < 2; mi++)
        #pragma unroll
        for (int ni = 0; ni < 8; ni++)
            #pragma unroll
            for (int j = 0; j < 4; j++) acc[mi][ni][j] = 0.f;

    float4 a4[4], b4[4];
    // load chunk 0
    #pragma unroll
    for (int i = 0; i < 4; i++) {
        int row = srow + i*32;
        int vg = vbase + row;
        a4[i] = (vg < V_) ? *(const float4*)&W_out[(size_t)vg*H_ + sf4*4]
                          : make_float4(0.f, 0.f, 0.f, 0.f);
        b4[i] = *(const float4*)&hsb[row*H_ + sf4*4];
    }
    {   // store chunk 0 into buffer 0
        float* Ab = As; float* Bb = Bs;
        #pragma unroll
        for (int i = 0; i < 4; i++) {
            int row = srow + i*32;
            Ab[(sf4*4+0)*133 + row] = tf32r(a4[i].x);
            Ab[(sf4*4+1)*133 + row] = tf32r(a4[i].y);
            Ab[(sf4*4+2)*133 + row] = tf32r(a4[i].z);
            Ab[(sf4*4+3)*133 + row] = tf32r(a4[i].w);
            Bb[(sf4*4+0)*133 + row] = tf32r(b4[i].x);
            Bb[(sf4*4+1)*133 + row] = tf32r(b4[i].y);
            Bb[(sf4*4+2)*133 + row] = tf32r(b4[i].z);
            Bb[(sf4*4+3)*133 + row] = tf32r(b4[i].w);
        }
    }
    __syncthreads();

    for (int kc = 0; kc < 8; kc++) {
        // prefetch chunk kc+1
        if (kc < 7) {
            int k = (kc + 1)*32 + sf4*4;
            #pragma unroll
            for (int i = 0; i < 4; i++) {
                int row = srow + i*32;
                int vg = vbase + row;
                a4[i] = (vg < V_) ? *(const float4*)&W_out[(size_t)vg*H_ + k]
                                  : make_float4(0.f, 0.f, 0.f, 0.f);
                b4[i] = *(const float4*)&hsb[row*H_ + k];
            }
        }
        // compute on buffer kc&1
        const float* Ab = As + (kc & 1)*OGBUF;
        const float* Bb = Bs + (kc & 1)*OGBUF;
        #pragma unroll
        for (int ks = 0; ks < 4; ks++) {
            const int k0 = ks*8;
            uint32_t afr[2][4];
            #pragma unroll
            for (int mi = 0; mi < 2; mi++) {
                int v0 = wv*32 + mi*16;
                afr[mi][0] = __float_as_uint(Ab[(k0+cq  )*133 + v0 + r    ]);
                afr[mi][1] = __float_as_uint(Ab[(k0+cq  )*133 + v0 + r + 8]);
                afr[mi][2] = __float_as_uint(Ab[(k0+cq+4)*133 + v0 + r    ]);
                afr[mi][3] = __float_as_uint(Ab[(k0+cq+4)*133 + v0 + r + 8]);
            }
            #pragma unroll
            for (int ni = 0; ni < 8; ni++) {
                int t0 = wt*64 + ni*8;
                uint32_t bfr[2];
                bfr[0] = __float_as_uint(Bb[(k0+cq  )*133 + t0 + r]);
                bfr[1] = __float_as_uint(Bb[(k0+cq+4)*133 + t0 + r]);
                mma_tf32_16x8x8(acc[0][ni], afr[0], bfr);
                mma_tf32_16x8x8(acc[1][ni], afr[1], bfr);
            }
        }
        // store prefetched chunk into the other buffer
        if (kc < 7) {
            float* An = As + ((kc + 1) & 1)*OGBUF;
            float* Bn = Bs + ((kc + 1) & 1)*OGBUF;
            #pragma unroll
            for (int i = 0; i < 4; i++) {
                int row = srow + i*32;
                An[(sf4*4+0)*133 + row] = tf32r(a4[i].x);
                An[(sf4*4+1)*133 + row] = tf32r(a4[i].y);
                An[(sf4*4+2)*133 + row] = tf32r(a4[i].z);
                An[(sf4*4+3)*133 + row] = tf32r(a4[i].w);
                Bn[(sf4*4+0)*133 + row] = tf32r(b4[i].x);
                Bn[(sf4*4+1)*133 + row] = tf32r(b4[i].y);
                Bn[(sf4*4+2)*133 + row] = tf32r(b4[i].z);
                Bn[(sf4*4+3)*133 + row] = tf32r(b4[i].w);
            }
        }
        __syncthreads();
    }

    // epilogue: c0,c1 -> (v0+r, t0+2cq); c2,c3 -> (v0+r+8, t0+2cq)
    #pragma unroll
    for (int mi = 0; mi < 2; mi++) {
        int vloc0 = wv*32 + mi*16 + r;
        int vloc1 = vloc0 + 8;
        int vg0 = vbase + vloc0, vg1 = vbase + vloc1;
        float bi0 = bsh[vloc0], bi1 = bsh[vloc1];
        #pragma unroll
        for (int ni = 0; ni < 8; ni++) {
            int t0 = wt*64 + ni*8 + 2*cq;
            if (vg0 < V_) {
                float2 o = make_float2(acc[mi][ni][0] + bi0, acc[mi][ni][1] + bi0);
                __stcg((float2*)&out[(size_t)b*((size_t)V_*T_) + (size_t)vg0*T_ + t0], o);
            }
            if (vg1 < V_) {
                float2 o = make_float2(acc[mi][ni][2] + bi1, acc[mi][ni][3] + bi1);
                __stcg((float2*)&out[(size_t)b*((size_t)V_*T_) + (size_t)vg1*T_ + t0], o);
            }
        }
    }
}

// ---------------- launch ----------------
extern "C" void kernel_launch(void* const* d_in, const int* in_sizes, int n_in,
                              void* d_out, int out_size)
{
    const int*   x      = (const int*)  d_in[0];
    const float* emb    = (const float*)d_in[1];
    const float* W_ih   = (const float*)d_in[2];
    const float* b_ih   = (const float*)d_in[3];
    const float* W_hh   = (const float*)d_in[4];
    const float* b_hh   = (const float*)d_in[5];
    const float* W_out  = (const float*)d_in[6];
    const float* b_out  = (const float*)d_in[7];
    const float* W_push = (const float*)d_in[8];
    const float* b_push = (const float*)d_in[9];
    const float* W_pop  = (const float*)d_in[10];
    const float* b_pop  = (const float*)d_in[11];
    const float* W_val  = (const float*)d_in[12];
    const float* b_val  = (const float*)d_in[13];
    float* out = (float*)d_out;

    const size_t R_SMEM = 51000 * sizeof(float);          // ~199.2 KB
    const size_t G_SMEM = (4*OGBUF + 128 + 64) * sizeof(float);  // ~68.9 KB
    static int configured = -1;
    if (configured < 0) {
        cudaFuncSetAttribute(recur_kernel, cudaFuncAttributeMaxDynamicSharedMemorySize,
                             (int)R_SMEM);
        cudaFuncSetAttribute(out_gemm, cudaFuncAttributeMaxDynamicSharedMemorySize,
                             (int)G_SMEM);
        configured = 1;
    }

    setup_kernel<<<64, 256>>>();
    recur_kernel<<<NCTA, NTHR, R_SMEM>>>(x, emb, W_ih, b_ih, W_hh, b_hh,
                                         W_pop, b_pop, W_push, b_push, b_val, W_val);
    dim3 g((V_ + 127) / 128, B_);
    out_gemm<<<g, 256, G_SMEM>>>(W_out, b_out, out);
}